// round 2
// baseline (speedup 1.0000x reference)
#include <cuda_runtime.h>
#include <math.h>
#include <stdint.h>

// ---------------- problem constants ----------------
#define Bc   2
#define Tc   16
#define Lc   256
#define Mc   512
#define Dc   1024
#define Hc   16
#define DHc  64
#define HTc  8
#define ROTc 32
#define TLc  4096            // T*L
#define NR   8192            // B*T*L rows
#define SCALEF 0.125f        // 1/sqrt(64)
#define NEGF  (-1000000000.0f)

// ---------------- scratch (device globals; no allocs allowed) ----------------
__device__ float g_buf1[(size_t)NR * Dc];        // xn / xn2 / xn3
__device__ float g_cn  [(size_t)Bc * Mc * Dc];   // LN(context)
__device__ float g_q   [(size_t)NR * Dc];        // cross-attn Q
__device__ float g_kv  [(size_t)Bc * Mc * 2048]; // cross-attn K|V
__device__ float g_oc  [(size_t)NR * Dc];        // cross-attn out, reused as temporal out (N x 512)
__device__ float g_x1  [(size_t)NR * Dc];
__device__ float g_qkv [(size_t)NR * 1536];
__device__ float g_x2  [(size_t)NR * Dc];
__device__ float g_h   [(size_t)NR * 4096];

// ---------------- LayerNorm: one block per row, D=1024 ----------------
__global__ void ln_kernel(const float* __restrict__ x, const float* __restrict__ g,
                          const float* __restrict__ b, float* __restrict__ y) {
    const int row = blockIdx.x;
    const int tid = threadIdx.x;                 // 256 threads
    const float4* xr = (const float4*)(x + (size_t)row * Dc);
    float4 v = xr[tid];
    float s  = v.x + v.y + v.z + v.w;
    float ss = v.x*v.x + v.y*v.y + v.z*v.z + v.w*v.w;

    __shared__ float rs[8], rss[8];
    for (int o = 16; o > 0; o >>= 1) {
        s  += __shfl_down_sync(0xffffffff, s,  o);
        ss += __shfl_down_sync(0xffffffff, ss, o);
    }
    const int wid = tid >> 5, lane = tid & 31;
    if (lane == 0) { rs[wid] = s; rss[wid] = ss; }
    __syncthreads();
    if (tid == 0) {
        float ts = 0.f, tss = 0.f;
        #pragma unroll
        for (int i = 0; i < 8; i++) { ts += rs[i]; tss += rss[i]; }
        rs[0] = ts; rss[0] = tss;
    }
    __syncthreads();
    const float mean = rs[0] * (1.0f / Dc);
    const float var  = rss[0] * (1.0f / Dc) - mean * mean;
    const float inv  = rsqrtf(var + 1e-5f);

    float4 gg = ((const float4*)g)[tid];
    float4 bb = ((const float4*)b)[tid];
    float4 o;
    o.x = (v.x - mean) * inv * gg.x + bb.x;
    o.y = (v.y - mean) * inv * gg.y + bb.y;
    o.z = (v.z - mean) * inv * gg.z + bb.z;
    o.w = (v.w - mean) * inv * gg.w + bb.w;
    ((float4*)(y + (size_t)row * Dc))[tid] = o;
}

// ---------------- SGEMM 64x64 tile, BK=16, 256 threads, 4x4/thread ----------------
// C[N,M] = A[N,K] @ B[K,M] (+bias[M]) (gelu) (+res[N,M])
template<int BIAS, int RES, int GELU>
__global__ void __launch_bounds__(256)
sgemm_kernel(const float* __restrict__ A, const float* __restrict__ Bm,
             const float* __restrict__ bias, const float* __restrict__ res,
             float* __restrict__ C, int Nn, int K, int Mm) {
    __shared__ float As[16][64];
    __shared__ float Bs[16][64];
    const int tid  = threadIdx.x;
    const int row0 = blockIdx.y * 64;
    const int col0 = blockIdx.x * 64;
    const int ty = tid >> 4, tx = tid & 15;

    const int arow  = tid >> 2;        // 0..63
    const int acol4 = (tid & 3) * 4;   // 0,4,8,12
    const int brow  = tid >> 4;        // 0..15
    const int bcol4 = (tid & 15) * 4;  // 0..60

    float acc[4][4] = {};
    for (int k0 = 0; k0 < K; k0 += 16) {
        float4 av = *(const float4*)(A + (size_t)(row0 + arow) * K + k0 + acol4);
        As[acol4 + 0][arow] = av.x;
        As[acol4 + 1][arow] = av.y;
        As[acol4 + 2][arow] = av.z;
        As[acol4 + 3][arow] = av.w;
        float4 bv = *(const float4*)(Bm + (size_t)(k0 + brow) * Mm + col0 + bcol4);
        *(float4*)&Bs[brow][bcol4] = bv;
        __syncthreads();
        #pragma unroll
        for (int kk = 0; kk < 16; kk++) {
            float4 ar = *(const float4*)&As[kk][ty * 4];
            float4 br = *(const float4*)&Bs[kk][tx * 4];
            float arr[4] = {ar.x, ar.y, ar.z, ar.w};
            float brr[4] = {br.x, br.y, br.z, br.w};
            #pragma unroll
            for (int i = 0; i < 4; i++)
                #pragma unroll
                for (int j = 0; j < 4; j++)
                    acc[i][j] += arr[i] * brr[j];
        }
        __syncthreads();
    }
    #pragma unroll
    for (int i = 0; i < 4; i++) {
        const int r = row0 + ty * 4 + i;
        #pragma unroll
        for (int j = 0; j < 4; j++) {
            const int c = col0 + tx * 4 + j;
            float v = acc[i][j];
            if (BIAS) v += bias[c];
            if (GELU) v = 0.5f * v * (1.0f + erff(v * 0.70710678118654752f));
            if (RES)  v += res[(size_t)r * Mm + c];
            C[(size_t)r * Mm + c] = v;
        }
    }
}

// ---------------- cross attention: block per (b,h,q-row) ----------------
__global__ void __launch_bounds__(256)
cross_attn_kernel(const float* __restrict__ q, const float* __restrict__ kv,
                  const int* __restrict__ cmask, float* __restrict__ o) {
    const int n = blockIdx.x;     // 0..4095
    const int h = blockIdx.y;     // 0..15
    const int b = blockIdx.z;     // 0..1
    const int tid = threadIdx.x;  // 256

    __shared__ float qs[64];
    __shared__ float p[Mc];
    __shared__ float red[256];

    const float* qrow = q + ((size_t)(b * TLc + n)) * 1024 + h * 64;
    if (tid < 64) qs[tid] = qrow[tid];
    __syncthreads();

    // scores
    #pragma unroll
    for (int m = tid; m < Mc; m += 256) {
        float s;
        if (cmask[b * Mc + m]) {
            const float* kr = kv + ((size_t)(b * Mc + m)) * 2048 + h * 64;
            float acc = 0.f;
            #pragma unroll
            for (int d = 0; d < 64; d += 4) {
                float4 kk = *(const float4*)(kr + d);
                acc += qs[d] * kk.x + qs[d + 1] * kk.y + qs[d + 2] * kk.z + qs[d + 3] * kk.w;
            }
            s = acc * SCALEF;
        } else {
            s = NEGF;
        }
        p[m] = s;
    }
    __syncthreads();

    // max
    red[tid] = fmaxf(p[tid], p[tid + 256]);
    __syncthreads();
    for (int st = 128; st > 0; st >>= 1) {
        if (tid < st) red[tid] = fmaxf(red[tid], red[tid + st]);
        __syncthreads();
    }
    const float mx = red[0];
    __syncthreads();

    // exp + sum
    float lsum = 0.f;
    #pragma unroll
    for (int m = tid; m < Mc; m += 256) {
        float e = __expf(p[m] - mx);
        p[m] = e;
        lsum += e;
    }
    red[tid] = lsum;
    __syncthreads();
    for (int st = 128; st > 0; st >>= 1) {
        if (tid < st) red[tid] += red[tid + st];
        __syncthreads();
    }
    const float inv = 1.0f / red[0];
    __syncthreads();

    // P @ V : thread = (part 0..3, d 0..63)
    const int d = tid & 63, part = tid >> 6;
    const float* vb = kv + ((size_t)b * Mc) * 2048 + 1024 + h * 64 + d;
    float acc = 0.f;
    const int m0 = part * 128;
    #pragma unroll 8
    for (int m = m0; m < m0 + 128; m++) acc += p[m] * vb[(size_t)m * 2048];
    red[tid] = acc;
    __syncthreads();
    if (tid < 64) {
        float v = (red[tid] + red[tid + 64] + red[tid + 128] + red[tid + 192]) * inv;
        o[((size_t)(b * TLc + n)) * 1024 + h * 64 + tid] = v;
    }
}

// ---------------- temporal attention (+RoPE): block per (b,l,h) ----------------
__global__ void __launch_bounds__(128)
temporal_attn_kernel(const float* __restrict__ qkv, const float* __restrict__ rope,
                     const int* __restrict__ amask, float* __restrict__ ot) {
    const int l = blockIdx.x;     // 0..255
    const int h = blockIdx.y;     // 0..7
    const int b = blockIdx.z;     // 0..1
    const int tid = threadIdx.x;  // 128

    __shared__ float qs[16][64], ks[16][64], vs[16][64];
    __shared__ float ss[16][17];

    for (int idx = tid; idx < 1024; idx += 128) {
        const int t = idx >> 6, d = idx & 63;
        const size_t base = ((size_t)((b * Tc + t) * Lc + l)) * 1536 + h * 64 + d;
        qs[t][d] = qkv[base];
        ks[t][d] = qkv[base + 512];
        vs[t][d] = qkv[base + 1024];
    }
    __syncthreads();

    // RoPE on first 32 dims of q,k (pairs r, r+16)
    for (int idx = tid; idx < 256; idx += 128) {
        const int t = idx >> 4, r = idx & 15;
        const float p0 = rope[t * ROTc + r];
        const float p1 = rope[t * ROTc + r + 16];
        const float c0 = cosf(p0), s0 = sinf(p0);
        const float c1 = cosf(p1), s1 = sinf(p1);
        float a = qs[t][r], bb = qs[t][r + 16];
        qs[t][r]      = a * c0 - bb * s0;
        qs[t][r + 16] = bb * c1 + a * s1;
        a = ks[t][r]; bb = ks[t][r + 16];
        ks[t][r]      = a * c0 - bb * s0;
        ks[t][r + 16] = bb * c1 + a * s1;
    }
    __syncthreads();

    // scores 16x16
    for (int idx = tid; idx < 256; idx += 128) {
        const int tq = idx >> 4, tk = idx & 15;
        float acc = 0.f;
        #pragma unroll
        for (int d = 0; d < 64; d++) acc += qs[tq][d] * ks[tk][d];
        ss[tq][tk] = amask[b * Tc + tk] ? acc * SCALEF : NEGF;
    }
    __syncthreads();

    // softmax per query row
    if (tid < 16) {
        float mx = -1e30f;
        #pragma unroll
        for (int tk = 0; tk < 16; tk++) mx = fmaxf(mx, ss[tid][tk]);
        float sum = 0.f;
        #pragma unroll
        for (int tk = 0; tk < 16; tk++) { float e = __expf(ss[tid][tk] - mx); ss[tid][tk] = e; sum += e; }
        const float inv = 1.0f / sum;
        #pragma unroll
        for (int tk = 0; tk < 16; tk++) ss[tid][tk] *= inv;
    }
    __syncthreads();

    // P @ V, query-mask, write (N x 512) layout
    for (int idx = tid; idx < 1024; idx += 128) {
        const int tq = idx >> 6, d = idx & 63;
        float acc = 0.f;
        #pragma unroll
        for (int tk = 0; tk < 16; tk++) acc += ss[tq][tk] * vs[tk][d];
        const float qm = amask[b * Tc + tq] ? 1.0f : 0.0f;
        ot[((size_t)((b * Tc + tq) * Lc + l)) * 512 + h * 64 + d] = acc * qm;
    }
}

// ---------------- launcher ----------------
extern "C" void kernel_launch(void* const* d_in, const int* in_sizes, int n_in,
                              void* d_out, int out_size) {
    const float* x        = (const float*)d_in[0];
    const float* context  = (const float*)d_in[1];
    const float* rope     = (const float*)d_in[2];
    const float* ca_ng    = (const float*)d_in[3];
    const float* ca_nb    = (const float*)d_in[4];
    const float* ca_cng   = (const float*)d_in[5];
    const float* ca_cnb   = (const float*)d_in[6];
    const float* ca_wq    = (const float*)d_in[7];
    const float* ca_wkv   = (const float*)d_in[8];
    const float* ca_wo    = (const float*)d_in[9];
    const float* ta_ng    = (const float*)d_in[10];
    const float* ta_nb    = (const float*)d_in[11];
    const float* ta_wqkv  = (const float*)d_in[12];
    const float* ta_bqkv  = (const float*)d_in[13];
    const float* ta_wo    = (const float*)d_in[14];
    const float* ff_ng    = (const float*)d_in[15];
    const float* ff_nb    = (const float*)d_in[16];
    const float* ff_w1    = (const float*)d_in[17];
    const float* ff_w2    = (const float*)d_in[18];
    const int*   cmask    = (const int*)d_in[19];
    const int*   amask    = (const int*)d_in[20];
    float* out = (float*)d_out;

    float *buf1, *cn, *qb, *kvb, *oc, *x1, *qkvb, *x2, *hb;
    cudaGetSymbolAddress((void**)&buf1, g_buf1);
    cudaGetSymbolAddress((void**)&cn,   g_cn);
    cudaGetSymbolAddress((void**)&qb,   g_q);
    cudaGetSymbolAddress((void**)&kvb,  g_kv);
    cudaGetSymbolAddress((void**)&oc,   g_oc);
    cudaGetSymbolAddress((void**)&x1,   g_x1);
    cudaGetSymbolAddress((void**)&qkvb, g_qkv);
    cudaGetSymbolAddress((void**)&x2,   g_x2);
    cudaGetSymbolAddress((void**)&hb,   g_h);

    // 1) xn = LN(x); cn = LN(context)
    ln_kernel<<<NR, 256>>>(x, ca_ng, ca_nb, buf1);
    ln_kernel<<<Bc * Mc, 256>>>(context, ca_cng, ca_cnb, cn);

    // 2) q = xn @ ca_wq ; kv = cn @ ca_wkv
    sgemm_kernel<0,0,0><<<dim3(1024/64, NR/64), 256>>>(buf1, ca_wq, nullptr, nullptr, qb, NR, 1024, 1024);
    sgemm_kernel<0,0,0><<<dim3(2048/64, (Bc*Mc)/64), 256>>>(cn, ca_wkv, nullptr, nullptr, kvb, Bc*Mc, 1024, 2048);

    // 3) cross attention
    cross_attn_kernel<<<dim3(TLc, Hc, Bc), 256>>>(qb, kvb, cmask, oc);

    // 4) x1 = x + o @ ca_wo
    sgemm_kernel<0,1,0><<<dim3(1024/64, NR/64), 256>>>(oc, ca_wo, nullptr, x, x1, NR, 1024, 1024);

    // 5) xn2 = LN(x1); qkv = xn2 @ ta_wqkv + bias
    ln_kernel<<<NR, 256>>>(x1, ta_ng, ta_nb, buf1);
    sgemm_kernel<1,0,0><<<dim3(1536/64, NR/64), 256>>>(buf1, ta_wqkv, ta_bqkv, nullptr, qkvb, NR, 1024, 1536);

    // 6) temporal attention (RoPE fused) -> oc reused as (N x 512)
    temporal_attn_kernel<<<dim3(Lc, HTc, Bc), 128>>>(qkvb, rope, amask, oc);

    // 7) x2 = x1 + ot @ ta_wo
    sgemm_kernel<0,1,0><<<dim3(1024/64, NR/64), 256>>>(oc, ta_wo, nullptr, x1, x2, NR, 512, 1024);

    // 8) xn3 = LN(x2); h = gelu(xn3 @ ff_w1); out = x2 + h @ ff_w2
    ln_kernel<<<NR, 256>>>(x2, ff_ng, ff_nb, buf1);
    sgemm_kernel<0,0,1><<<dim3(4096/64, NR/64), 256>>>(buf1, ff_w1, nullptr, nullptr, hb, NR, 1024, 4096);
    sgemm_kernel<0,1,0><<<dim3(1024/64, NR/64), 256>>>(hb, ff_w2, nullptr, x2, out, NR, 4096, 1024);
}